// round 9
// baseline (speedup 1.0000x reference)
#include <cuda_runtime.h>
#include <cuda_bf16.h>
#include <math.h>

// Problem constants (fixed shapes from reference)
#define N_NODES 40000
#define N_EDGES 640000
#define IN_CH   128
#define HID_CH  256
#define EDGE_DIM 64
#define N_SAMP  2048
#define N_QUERY (1 + 2*N_SAMP)   // 4097

// packed fp32x2 helpers (sm_103a; exact fp32 element-wise semantics)
#define FMA2(d,a,b,c) asm("fma.rn.f32x2 %0, %1, %2, %3;" : "=l"(d) : "l"(a), "l"(b), "l"(c))
#define PK2(o, lo, hi) asm("mov.b64 %0, {%1, %2};" : "=l"(o) : "f"(lo), "f"(hi))
#define UPK2(lo, hi, in) asm("mov.b64 {%0, %1}, %2;" : "=f"(lo), "=f"(hi) : "l"(in))

// ---------------- device scratch (no allocations allowed) ----------------
__device__ __align__(128) float g_agg[(size_t)N_NODES * IN_CH];  // rows zeroed lazily
__device__ unsigned char g_mask[N_NODES];   // zero-init; invariant: zero at entry
__device__ int   g_nodes[N_QUERY];
__device__ int   g_active[N_EDGES];
__device__ int   g_count;
__device__ __align__(128) float g_emb[(size_t)N_QUERY * HID_CH];
__device__ __align__(128) float g_center[HID_CH];
__device__ float g_scores[3];   // [0]=pos_sum, [1]=neg_sum, [2]=thr_score

// ---------------- kernel A: build mask, node list, zero needed agg rows ----
__global__ void build_mask_kernel(const int* __restrict__ pos,
                                  const int* __restrict__ neg) {
    int b = blockIdx.x;
    int node;
    if (b == 0)          node = 0;
    else if (b <= N_SAMP) node = pos[b - 1];
    else                 node = neg[b - 1 - N_SAMP];
    if (threadIdx.x == 0) {
        g_mask[node] = 1;
        g_nodes[b] = node;
        if (b == 0) g_count = 0;
    }
    g_agg[(size_t)node * IN_CH + threadIdx.x] = 0.0f;  // duplicates benign
}

// ---------------- kernel B1: warp-aggregated edge filter ------------------
__global__ void edge_filter_kernel(const int* __restrict__ dst) {
    int t = blockIdx.x * blockDim.x + threadIdx.x;
    int e0 = t * 4;                       // N_EDGES % 4 == 0
    int4 d4 = *(const int4*)(dst + e0);
    int lane = threadIdx.x & 31;
    #pragma unroll
    for (int i = 0; i < 4; i++) {
        int d = (i == 0) ? d4.x : (i == 1) ? d4.y : (i == 2) ? d4.z : d4.w;
        bool hit = (g_mask[d] != 0);
        unsigned bal = __ballot_sync(0xffffffffu, hit);
        int slot = 0;
        if (lane == 0 && bal) slot = atomicAdd(&g_count, __popc(bal));
        slot = __shfl_sync(0xffffffffu, slot, 0);
        if (hit) g_active[slot + __popc(bal & ((1u << lane) - 1))] = e0 + i;
    }
}

// ---------------- kernel B2: batched projection, channel-pair f32x2 -------
// 256 threads, 64 edges/batch, 4 threads/edge staging DUPLICATED {a,a} pairs.
// Inner loop per k: 1 LDS.128 (w01,w23 pairs) + 4 LDS.128 (2 edges' {a,a})
// + 16 FMA2 — zero MOVs. Warp q: edges q*8..q*8+7; lane cg: channels cg*4..+3.
#define E_BLK 64
#define SAD_PAD 132   // floats per row: 132*4=528B = 33*16 (16B-aligned rows)
__global__ __launch_bounds__(256, 2)
void edge_scatter_kernel(const int* __restrict__ src,
                         const int* __restrict__ dst,
                         const float* __restrict__ edge_attr,
                         const float* __restrict__ x,
                         const float* __restrict__ We,
                         const float* __restrict__ be) {
    __shared__ __align__(16) float sWe[EDGE_DIM * IN_CH];     // 32 KB
    __shared__ __align__(16) float sAd[EDGE_DIM][SAD_PAD];    // 33 KB (dup pairs)
    __shared__ int sSrc[E_BLK], sDst[E_BLK];

    for (int i = threadIdx.x; i < EDGE_DIM * IN_CH / 4; i += 256)
        ((float4*)sWe)[i] = ((const float4*)We)[i];

    int tid  = threadIdx.x;
    int jj   = tid >> 2;        // edge slot 0..63
    int quarter = tid & 3;      // 16-float quarter of the 64-float attr row
    int nact = g_count;         // stream-ordered after B1
    int nbatch = (nact + E_BLK - 1) / E_BLK;

    // prologue: prefetch first batch into registers (16 floats/thread)
    float4 r[4];
    #pragma unroll
    for (int i = 0; i < 4; i++) r[i] = make_float4(0.f,0.f,0.f,0.f);
    int pS = 0, pD = -1;
    int batch = blockIdx.x;
    if (batch < nbatch) {
        int gi = batch * E_BLK + jj;
        if (gi < nact) {
            int e = g_active[gi];
            const float4* gp = (const float4*)(edge_attr + (size_t)e * EDGE_DIM + quarter * 16);
            #pragma unroll
            for (int i = 0; i < 4; i++) r[i] = gp[i];
            if (quarter == 0) { pS = src[e]; pD = dst[e]; }
        }
    }

    int cg = tid & 31, c = cg * 4, q = tid >> 5;
    int ebase = q * 8;
    const unsigned long long bias01 = *(const unsigned long long*)(be + c);
    const unsigned long long bias23 = *(const unsigned long long*)(be + c + 2);

    for (; batch < nbatch; batch += gridDim.x) {
        __syncthreads();   // previous batch's smem readers done
        // commit staged registers as duplicated pairs: rows k0..k0+15, col 2*jj
        int k0 = quarter * 16;
        #pragma unroll
        for (int i = 0; i < 4; i++) {
            *(float2*)(&sAd[k0 + i*4 + 0][2*jj]) = make_float2(r[i].x, r[i].x);
            *(float2*)(&sAd[k0 + i*4 + 1][2*jj]) = make_float2(r[i].y, r[i].y);
            *(float2*)(&sAd[k0 + i*4 + 2][2*jj]) = make_float2(r[i].z, r[i].z);
            *(float2*)(&sAd[k0 + i*4 + 3][2*jj]) = make_float2(r[i].w, r[i].w);
        }
        if (quarter == 0) { sSrc[jj] = pS; sDst[jj] = pD; }

        // prefetch next batch (LDGs in flight across compute below)
        int nb = batch + gridDim.x;
        #pragma unroll
        for (int i = 0; i < 4; i++) r[i] = make_float4(0.f,0.f,0.f,0.f);
        pD = -1;
        if (nb < nbatch) {
            int gi = nb * E_BLK + jj;
            if (gi < nact) {
                int e = g_active[gi];
                const float4* gp = (const float4*)(edge_attr + (size_t)e * EDGE_DIM + quarter * 16);
                #pragma unroll
                for (int i = 0; i < 4; i++) r[i] = gp[i];
                if (quarter == 0) { pS = src[e]; pD = dst[e]; }
            }
        }
        __syncthreads();   // staged data visible

        // compute: 8 edges x 4 channels; acc[e][0]={c,c+1}, acc[e][1]={c+2,c+3}
        unsigned long long acc[8][2];
        #pragma unroll
        for (int j = 0; j < 8; j++) { acc[j][0] = bias01; acc[j][1] = bias23; }

        #pragma unroll 4
        for (int k = 0; k < EDGE_DIM; k++) {
            ulonglong2 wp = *(const ulonglong2*)(sWe + k * IN_CH + c); // {w0,w1},{w2,w3}
            #pragma unroll
            for (int jp = 0; jp < 4; jp++) {
                // {a_e,a_e},{a_e1,a_e1} for edges e=ebase+2jp, e1=e+1
                ulonglong2 ap = *(const ulonglong2*)(&sAd[k][2*(ebase + 2*jp)]);
                FMA2(acc[2*jp  ][0], ap.x, wp.x, acc[2*jp  ][0]);
                FMA2(acc[2*jp  ][1], ap.x, wp.y, acc[2*jp  ][1]);
                FMA2(acc[2*jp+1][0], ap.y, wp.x, acc[2*jp+1][0]);
                FMA2(acc[2*jp+1][1], ap.y, wp.y, acc[2*jp+1][1]);
            }
        }

        // tail: +x[src], relu, vector RED
        #pragma unroll
        for (int j = 0; j < 8; j++) {
            int e = ebase + j;
            int d = sDst[e];
            if (d >= 0) {
                float v0, v1, v2, v3;
                UPK2(v0, v1, acc[j][0]);
                UPK2(v2, v3, acc[j][1]);
                int s = sSrc[e];
                float4 xv = *(const float4*)(x + (size_t)s * IN_CH + c);
                v0 = fmaxf(v0 + xv.x, 0.0f);
                v1 = fmaxf(v1 + xv.y, 0.0f);
                v2 = fmaxf(v2 + xv.z, 0.0f);
                v3 = fmaxf(v3 + xv.w, 0.0f);
                float* ap = g_agg + (size_t)d * IN_CH + c;
                asm volatile("red.global.v4.f32.add [%0], {%1, %2, %3, %4};"
                             :: "l"(ap), "f"(v0), "f"(v1), "f"(v2), "f"(v3)
                             : "memory");
            }
        }
    }
}

// ---------------- kernel C: MLP on 4097 query rows ------------------------
// Small tile for occupancy: 8 rows/block, 513 blocks, ~3.5 blocks/SM.
// Thread = output channel c; 4 f32x2 row-pair accumulators.
#define MROWS 8
#define MPAD  12    // 12*4=48B rows (16B aligned)
__global__ __launch_bounds__(256, 4)
void mlp_kernel(const float* __restrict__ x,
                const float* __restrict__ W1, const float* __restrict__ b1,
                const float* __restrict__ W2, const float* __restrict__ b2) {
    __shared__ __align__(16) float sh_t[IN_CH][MPAD];   // 6 KB
    __shared__ __align__(16) float st_t[HID_CH][MPAD];  // 12 KB
    int tid = threadIdx.x;
    int r0  = blockIdx.x * MROWS;

    for (int j = tid; j < MROWS * IN_CH; j += 256) {
        int r = j >> 7, k = j & (IN_CH - 1);
        int idx = r0 + r;
        float v = 0.0f;
        if (idx < N_QUERY) {
            int node = g_nodes[idx];
            size_t off = (size_t)node * IN_CH + k;
            v = x[off] + g_agg[off];
        }
        sh_t[k][r] = v;
    }
    __syncthreads();

    int c = tid;
    unsigned long long acc[4];
    {
        float bb = __ldg(b1 + c);
        unsigned long long bp; PK2(bp, bb, bb);
        #pragma unroll
        for (int i = 0; i < 4; i++) acc[i] = bp;
    }
    #pragma unroll 8
    for (int k = 0; k < IN_CH; k++) {
        float w = __ldg(W1 + k * HID_CH + c);
        unsigned long long wp; PK2(wp, w, w);
        ulonglong2 a01 = *(const ulonglong2*)(&sh_t[k][0]);
        ulonglong2 a23 = *(const ulonglong2*)(&sh_t[k][4]);
        FMA2(acc[0], a01.x, wp, acc[0]);
        FMA2(acc[1], a01.y, wp, acc[1]);
        FMA2(acc[2], a23.x, wp, acc[2]);
        FMA2(acc[3], a23.y, wp, acc[3]);
    }
    #pragma unroll
    for (int rp = 0; rp < 4; rp++) {
        float lo, hi; UPK2(lo, hi, acc[rp]);
        *(float2*)(&st_t[c][rp * 2]) =
            make_float2(fmaxf(lo, 0.0f), fmaxf(hi, 0.0f));
    }
    __syncthreads();

    {
        float bb = __ldg(b2 + c);
        unsigned long long bp; PK2(bp, bb, bb);
        #pragma unroll
        for (int i = 0; i < 4; i++) acc[i] = bp;
    }
    #pragma unroll 8
    for (int k = 0; k < HID_CH; k++) {
        float w = __ldg(W2 + k * HID_CH + c);
        unsigned long long wp; PK2(wp, w, w);
        ulonglong2 a01 = *(const ulonglong2*)(&st_t[k][0]);
        ulonglong2 a23 = *(const ulonglong2*)(&st_t[k][4]);
        FMA2(acc[0], a01.x, wp, acc[0]);
        FMA2(acc[1], a01.y, wp, acc[1]);
        FMA2(acc[2], a23.x, wp, acc[2]);
        FMA2(acc[3], a23.y, wp, acc[3]);
    }
    #pragma unroll
    for (int rp = 0; rp < 4; rp++) {
        float lo, hi; UPK2(lo, hi, acc[rp]);
        int i0 = r0 + rp * 2;
        if (i0 < N_QUERY)     g_emb[(size_t)i0 * HID_CH + c] = lo;
        if (i0 + 1 < N_QUERY) g_emb[(size_t)(i0 + 1) * HID_CH + c] = hi;
    }
}

// ---------------- block reduction helper (256 threads) --------------------
__device__ __forceinline__ float block_reduce_256(float v, float* red) {
    #pragma unroll
    for (int o = 16; o; o >>= 1) v += __shfl_down_sync(0xffffffffu, v, o);
    int lane = threadIdx.x & 31, w = threadIdx.x >> 5;
    __syncthreads();
    if (lane == 0) red[w] = v;
    __syncthreads();
    if (threadIdx.x == 0) {
        float s = 0.0f;
        #pragma unroll
        for (int i = 0; i < 8; i++) s += red[i];
        red[8] = s;
    }
    __syncthreads();
    return red[8];
}

// ---------------- kernel D1: center + thresholding score ------------------
__global__ void center_kernel(const float* __restrict__ thr_node) {
    __shared__ float red[9];
    int c = threadIdx.x;
    float e0 = g_emb[c];
    float ss = block_reduce_256(e0 * e0, red);
    float cen = e0 / fmaxf(sqrtf(ss), 1e-12f);
    g_center[c] = cen;

    float t = thr_node[c];
    float ts = block_reduce_256(t * t, red);
    float tn = t / fmaxf(sqrtf(ts), 1e-12f);

    float dot = block_reduce_256(cen * tn, red);
    if (c == 0) {
        g_scores[2] = dot;
        g_scores[0] = 0.0f;
        g_scores[1] = 0.0f;
    }
}

// ---------------- kernel D2: warp-per-row scores + mask clear -------------
__global__ __launch_bounds__(256)
void score_kernel() {
    __shared__ float sPos, sNeg;
    if (threadIdx.x == 0) { sPos = 0.0f; sNeg = 0.0f; }
    __syncthreads();

    int warp = threadIdx.x >> 5;
    int lane = threadIdx.x & 31;
    int row  = 1 + blockIdx.x * 8 + warp;       // rows 1..4096
    const float* v = g_emb + (size_t)row * HID_CH + lane * 8;
    const float* cen = g_center + lane * 8;

    float4 a = *(const float4*)(v);
    float4 b = *(const float4*)(v + 4);
    float4 ca = *(const float4*)(cen);
    float4 cb = *(const float4*)(cen + 4);

    float ss = a.x*a.x + a.y*a.y + a.z*a.z + a.w*a.w
             + b.x*b.x + b.y*b.y + b.z*b.z + b.w*b.w;
    float dd = a.x*ca.x + a.y*ca.y + a.z*ca.z + a.w*ca.w
             + b.x*cb.x + b.y*cb.y + b.z*cb.z + b.w*cb.w;
    #pragma unroll
    for (int o = 16; o; o >>= 1) {
        ss += __shfl_down_sync(0xffffffffu, ss, o);
        dd += __shfl_down_sync(0xffffffffu, dd, o);
    }
    if (lane == 0) {
        float score = dd / fmaxf(sqrtf(ss), 1e-12f);
        atomicAdd((row <= N_SAMP) ? &sPos : &sNeg, score);
    }
    __syncthreads();
    if (threadIdx.x == 0) {
        if (sPos != 0.0f) atomicAdd(&g_scores[0], sPos);
        if (sNeg != 0.0f) atomicAdd(&g_scores[1], sNeg);
    }

    // restore invariant: mask zero for next call (512 blocks x 256 >= 40000)
    int g = blockIdx.x * 256 + threadIdx.x;
    if (g < N_NODES) g_mask[g] = 0;
}

// ---------------- kernel E: final loss ------------------------------------
__global__ void finalize_kernel(float* __restrict__ out) {
    float pos_mean = g_scores[0] * (1.0f / N_SAMP);
    float neg_mean = g_scores[1] * (1.0f / N_SAMP);
    float th = g_scores[2];
    float sp = 1.0f / (1.0f + expf(-(pos_mean - th)));   // T = 1
    float sn = 1.0f / (1.0f + expf(-(th - neg_mean)));
    float pl = logf(fmaxf(sp, 1e-12f));
    float nl = logf(fmaxf(sn, 1e-12f));
    out[0] = -pl - nl;
}

// ---------------- launch ---------------------------------------------------
extern "C" void kernel_launch(void* const* d_in, const int* in_sizes, int n_in,
                              void* d_out, int out_size) {
    const float* x    = (const float*)d_in[0];
    const int*   ei   = (const int*)d_in[1];     // int32 (JAX x64 disabled)
    const float* ea   = (const float*)d_in[2];
    const int*   pos  = (const int*)d_in[3];
    const int*   neg  = (const int*)d_in[4];
    const float* We   = (const float*)d_in[5];
    const float* be   = (const float*)d_in[6];
    const float* W1   = (const float*)d_in[7];
    const float* b1   = (const float*)d_in[8];
    const float* W2   = (const float*)d_in[9];
    const float* b2   = (const float*)d_in[10];
    const float* thr  = (const float*)d_in[11];
    float* out = (float*)d_out;

    const int* src = ei;            // edge_index[0]
    const int* dst = ei + N_EDGES;  // edge_index[1]

    build_mask_kernel<<<N_QUERY, IN_CH>>>(pos, neg);
    edge_filter_kernel<<<N_EDGES / 4 / 256, 256>>>(dst);
    edge_scatter_kernel<<<296, 256>>>(src, dst, ea, x, We, be);
    mlp_kernel<<<(N_QUERY + MROWS - 1) / MROWS, 256>>>(x, W1, b1, W2, b2);
    center_kernel<<<1, 256>>>(thr);
    score_kernel<<<N_SAMP / 4, 256>>>();
    finalize_kernel<<<1, 1>>>(out);
}

// round 11
// speedup vs baseline: 1.0280x; 1.0280x over previous
#include <cuda_runtime.h>
#include <cuda_bf16.h>
#include <math.h>

// Problem constants (fixed shapes from reference)
#define N_NODES 40000
#define N_EDGES 640000
#define IN_CH   128
#define HID_CH  256
#define EDGE_DIM 64
#define N_SAMP  2048
#define N_QUERY (1 + 2*N_SAMP)   // 4097

// packed fp32x2 helpers (sm_103a; exact fp32 element-wise semantics)
#define FMA2(d,a,b,c) asm("fma.rn.f32x2 %0, %1, %2, %3;" : "=l"(d) : "l"(a), "l"(b), "l"(c))
#define PK2(o, lo, hi) asm("mov.b64 %0, {%1, %2};" : "=l"(o) : "f"(lo), "f"(hi))
#define UPK2(lo, hi, in) asm("mov.b64 {%0, %1}, %2;" : "=f"(lo), "=f"(hi) : "l"(in))

// ---------------- device scratch (no allocations allowed) ----------------
__device__ __align__(128) float g_agg[(size_t)N_NODES * IN_CH];  // rows zeroed lazily
__device__ unsigned char g_mask[N_NODES];   // zero-init; invariant: zero at entry
__device__ int   g_nodes[N_QUERY];
__device__ int   g_active[N_EDGES];
__device__ int   g_count;
__device__ __align__(128) float g_emb[(size_t)N_QUERY * HID_CH];
__device__ __align__(128) float g_center[HID_CH];
__device__ float g_scores[3];   // [0]=pos_sum, [1]=neg_sum, [2]=thr_score

// ---------------- kernel A: build mask, node list, zero needed agg rows ----
__global__ void build_mask_kernel(const int* __restrict__ pos,
                                  const int* __restrict__ neg) {
    int b = blockIdx.x;
    int node;
    if (b == 0)          node = 0;
    else if (b <= N_SAMP) node = pos[b - 1];
    else                 node = neg[b - 1 - N_SAMP];
    if (threadIdx.x == 0) {
        g_mask[node] = 1;
        g_nodes[b] = node;
        if (b == 0) g_count = 0;
    }
    g_agg[(size_t)node * IN_CH + threadIdx.x] = 0.0f;  // duplicates benign
}

// ---------------- kernel B1: warp-aggregated edge filter ------------------
__global__ void edge_filter_kernel(const int* __restrict__ dst) {
    int t = blockIdx.x * blockDim.x + threadIdx.x;
    int e0 = t * 4;                       // N_EDGES % 4 == 0
    int4 d4 = *(const int4*)(dst + e0);
    int lane = threadIdx.x & 31;
    #pragma unroll
    for (int i = 0; i < 4; i++) {
        int d = (i == 0) ? d4.x : (i == 1) ? d4.y : (i == 2) ? d4.z : d4.w;
        bool hit = (g_mask[d] != 0);
        unsigned bal = __ballot_sync(0xffffffffu, hit);
        int slot = 0;
        if (lane == 0 && bal) slot = atomicAdd(&g_count, __popc(bal));
        slot = __shfl_sync(0xffffffffu, slot, 0);
        if (hit) g_active[slot + __popc(bal & ((1u << lane) - 1))] = e0 + i;
    }
}

// ---------------- kernel B2: batched projection, channel-pair f32x2 -------
// 256 threads, 64 edges/batch, 4 threads/edge staging DUPLICATED {a,a} pairs.
// Inner loop per k: 1 LDS.128 (w01,w23 pairs) + 4 LDS.128 (2 edges' {a,a})
// + 16 FMA2 — zero MOVs. Warp q: edges q*8..q*8+7; lane cg: channels cg*4..+3.
#define E_BLK 64
#define SAD_PAD 132   // floats per row: 132*4=528B = 33*16 (16B-aligned rows)
__global__ __launch_bounds__(256, 2)
void edge_scatter_kernel(const int* __restrict__ src,
                         const int* __restrict__ dst,
                         const float* __restrict__ edge_attr,
                         const float* __restrict__ x,
                         const float* __restrict__ We,
                         const float* __restrict__ be) {
    __shared__ __align__(16) float sWe[EDGE_DIM * IN_CH];     // 32 KB
    __shared__ __align__(16) float sAd[EDGE_DIM][SAD_PAD];    // 33 KB (dup pairs)
    __shared__ int sSrc[E_BLK], sDst[E_BLK];

    for (int i = threadIdx.x; i < EDGE_DIM * IN_CH / 4; i += 256)
        ((float4*)sWe)[i] = ((const float4*)We)[i];

    int tid  = threadIdx.x;
    int jj   = tid >> 2;        // edge slot 0..63
    int quarter = tid & 3;      // 16-float quarter of the 64-float attr row
    int nact = g_count;         // stream-ordered after B1
    int nbatch = (nact + E_BLK - 1) / E_BLK;

    // prologue: prefetch first batch into registers (16 floats/thread)
    float4 r[4];
    #pragma unroll
    for (int i = 0; i < 4; i++) r[i] = make_float4(0.f,0.f,0.f,0.f);
    int pS = 0, pD = -1;
    int batch = blockIdx.x;
    if (batch < nbatch) {
        int gi = batch * E_BLK + jj;
        if (gi < nact) {
            int e = g_active[gi];
            const float4* gp = (const float4*)(edge_attr + (size_t)e * EDGE_DIM + quarter * 16);
            #pragma unroll
            for (int i = 0; i < 4; i++) r[i] = gp[i];
            if (quarter == 0) { pS = src[e]; pD = dst[e]; }
        }
    }

    int cg = tid & 31, c = cg * 4, q = tid >> 5;
    int ebase = q * 8;
    const unsigned long long bias01 = *(const unsigned long long*)(be + c);
    const unsigned long long bias23 = *(const unsigned long long*)(be + c + 2);

    for (; batch < nbatch; batch += gridDim.x) {
        __syncthreads();   // previous batch's smem readers done
        // commit staged registers as duplicated pairs: rows k0..k0+15, col 2*jj
        int k0 = quarter * 16;
        #pragma unroll
        for (int i = 0; i < 4; i++) {
            *(float2*)(&sAd[k0 + i*4 + 0][2*jj]) = make_float2(r[i].x, r[i].x);
            *(float2*)(&sAd[k0 + i*4 + 1][2*jj]) = make_float2(r[i].y, r[i].y);
            *(float2*)(&sAd[k0 + i*4 + 2][2*jj]) = make_float2(r[i].z, r[i].z);
            *(float2*)(&sAd[k0 + i*4 + 3][2*jj]) = make_float2(r[i].w, r[i].w);
        }
        if (quarter == 0) { sSrc[jj] = pS; sDst[jj] = pD; }

        // prefetch next batch (LDGs in flight across compute below)
        int nb = batch + gridDim.x;
        #pragma unroll
        for (int i = 0; i < 4; i++) r[i] = make_float4(0.f,0.f,0.f,0.f);
        pD = -1;
        if (nb < nbatch) {
            int gi = nb * E_BLK + jj;
            if (gi < nact) {
                int e = g_active[gi];
                const float4* gp = (const float4*)(edge_attr + (size_t)e * EDGE_DIM + quarter * 16);
                #pragma unroll
                for (int i = 0; i < 4; i++) r[i] = gp[i];
                if (quarter == 0) { pS = src[e]; pD = dst[e]; }
            }
        }
        __syncthreads();   // staged data visible

        // compute: 8 edges x 4 channels; acc[e][0]={c,c+1}, acc[e][1]={c+2,c+3}
        unsigned long long acc[8][2];
        #pragma unroll
        for (int j = 0; j < 8; j++) { acc[j][0] = bias01; acc[j][1] = bias23; }

        #pragma unroll 4
        for (int k = 0; k < EDGE_DIM; k++) {
            ulonglong2 wp = *(const ulonglong2*)(sWe + k * IN_CH + c); // {w0,w1},{w2,w3}
            #pragma unroll
            for (int jp = 0; jp < 4; jp++) {
                // {a_e,a_e},{a_e1,a_e1} for edges e=ebase+2jp, e1=e+1
                ulonglong2 ap = *(const ulonglong2*)(&sAd[k][2*(ebase + 2*jp)]);
                FMA2(acc[2*jp  ][0], ap.x, wp.x, acc[2*jp  ][0]);
                FMA2(acc[2*jp  ][1], ap.x, wp.y, acc[2*jp  ][1]);
                FMA2(acc[2*jp+1][0], ap.y, wp.x, acc[2*jp+1][0]);
                FMA2(acc[2*jp+1][1], ap.y, wp.y, acc[2*jp+1][1]);
            }
        }

        // tail: +x[src], relu, vector RED
        #pragma unroll
        for (int j = 0; j < 8; j++) {
            int e = ebase + j;
            int d = sDst[e];
            if (d >= 0) {
                float v0, v1, v2, v3;
                UPK2(v0, v1, acc[j][0]);
                UPK2(v2, v3, acc[j][1]);
                int s = sSrc[e];
                float4 xv = *(const float4*)(x + (size_t)s * IN_CH + c);
                v0 = fmaxf(v0 + xv.x, 0.0f);
                v1 = fmaxf(v1 + xv.y, 0.0f);
                v2 = fmaxf(v2 + xv.z, 0.0f);
                v3 = fmaxf(v3 + xv.w, 0.0f);
                float* ap = g_agg + (size_t)d * IN_CH + c;
                asm volatile("red.global.v4.f32.add [%0], {%1, %2, %3, %4};"
                             :: "l"(ap), "f"(v0), "f"(v1), "f"(v2), "f"(v3)
                             : "memory");
            }
        }
    }
}

// ---------------- kernel C: MLP on 4097 query rows ------------------------
// 16 rows/block, 257 blocks, 3 blocks/SM target. Thread = output channel.
// Per k: 1 LDG(w) + 4 broadcast LDS.128 + 8 FMA2 -> FMA-pipe bound.
#define MROWS 16
#define MPAD  20    // 20*4=80B rows (16B aligned)
__global__ __launch_bounds__(256, 3)
void mlp_kernel(const float* __restrict__ x,
                const float* __restrict__ W1, const float* __restrict__ b1,
                const float* __restrict__ W2, const float* __restrict__ b2) {
    __shared__ __align__(16) float sh_t[IN_CH][MPAD];   // 10.2 KB
    __shared__ __align__(16) float st_t[HID_CH][MPAD];  // 20.5 KB
    int tid = threadIdx.x;
    int r0  = blockIdx.x * MROWS;

    for (int j = tid; j < MROWS * IN_CH; j += 256) {
        int r = j >> 7, k = j & (IN_CH - 1);
        int idx = r0 + r;
        float v = 0.0f;
        if (idx < N_QUERY) {
            int node = g_nodes[idx];
            size_t off = (size_t)node * IN_CH + k;
            v = x[off] + g_agg[off];
        }
        sh_t[k][r] = v;
    }
    __syncthreads();

    int c = tid;
    unsigned long long acc[8];
    {
        float bb = __ldg(b1 + c);
        unsigned long long bp; PK2(bp, bb, bb);
        #pragma unroll
        for (int i = 0; i < 8; i++) acc[i] = bp;
    }
    #pragma unroll 4
    for (int k = 0; k < IN_CH; k++) {
        float w = __ldg(W1 + k * HID_CH + c);
        unsigned long long wp; PK2(wp, w, w);
        #pragma unroll
        for (int rq = 0; rq < 4; rq++) {
            ulonglong2 a2 = *(const ulonglong2*)(&sh_t[k][rq * 4]);
            FMA2(acc[rq*2  ], a2.x, wp, acc[rq*2  ]);
            FMA2(acc[rq*2+1], a2.y, wp, acc[rq*2+1]);
        }
    }
    #pragma unroll
    for (int rp = 0; rp < 8; rp++) {
        float lo, hi; UPK2(lo, hi, acc[rp]);
        *(float2*)(&st_t[c][rp * 2]) =
            make_float2(fmaxf(lo, 0.0f), fmaxf(hi, 0.0f));
    }
    __syncthreads();

    {
        float bb = __ldg(b2 + c);
        unsigned long long bp; PK2(bp, bb, bb);
        #pragma unroll
        for (int i = 0; i < 8; i++) acc[i] = bp;
    }
    #pragma unroll 4
    for (int k = 0; k < HID_CH; k++) {
        float w = __ldg(W2 + k * HID_CH + c);
        unsigned long long wp; PK2(wp, w, w);
        #pragma unroll
        for (int rq = 0; rq < 4; rq++) {
            ulonglong2 a2 = *(const ulonglong2*)(&st_t[k][rq * 4]);
            FMA2(acc[rq*2  ], a2.x, wp, acc[rq*2  ]);
            FMA2(acc[rq*2+1], a2.y, wp, acc[rq*2+1]);
        }
    }
    #pragma unroll
    for (int rp = 0; rp < 8; rp++) {
        float lo, hi; UPK2(lo, hi, acc[rp]);
        int i0 = r0 + rp * 2;
        if (i0 < N_QUERY)     g_emb[(size_t)i0 * HID_CH + c] = lo;
        if (i0 + 1 < N_QUERY) g_emb[(size_t)(i0 + 1) * HID_CH + c] = hi;
    }
}

// ---------------- block reduction helper (256 threads) --------------------
__device__ __forceinline__ float block_reduce_256(float v, float* red) {
    #pragma unroll
    for (int o = 16; o; o >>= 1) v += __shfl_down_sync(0xffffffffu, v, o);
    int lane = threadIdx.x & 31, w = threadIdx.x >> 5;
    __syncthreads();
    if (lane == 0) red[w] = v;
    __syncthreads();
    if (threadIdx.x == 0) {
        float s = 0.0f;
        #pragma unroll
        for (int i = 0; i < 8; i++) s += red[i];
        red[8] = s;
    }
    __syncthreads();
    return red[8];
}

// ---------------- kernel D1: center + thresholding score ------------------
__global__ void center_kernel(const float* __restrict__ thr_node) {
    __shared__ float red[9];
    int c = threadIdx.x;
    float e0 = g_emb[c];
    float ss = block_reduce_256(e0 * e0, red);
    float cen = e0 / fmaxf(sqrtf(ss), 1e-12f);
    g_center[c] = cen;

    float t = thr_node[c];
    float ts = block_reduce_256(t * t, red);
    float tn = t / fmaxf(sqrtf(ts), 1e-12f);

    float dot = block_reduce_256(cen * tn, red);
    if (c == 0) {
        g_scores[2] = dot;
        g_scores[0] = 0.0f;
        g_scores[1] = 0.0f;
    }
}

// ---------------- kernel D2: warp-per-row scores + mask clear -------------
__global__ __launch_bounds__(256)
void score_kernel() {
    __shared__ float sPos, sNeg;
    if (threadIdx.x == 0) { sPos = 0.0f; sNeg = 0.0f; }
    __syncthreads();

    int warp = threadIdx.x >> 5;
    int lane = threadIdx.x & 31;
    int row  = 1 + blockIdx.x * 8 + warp;       // rows 1..4096
    const float* v = g_emb + (size_t)row * HID_CH + lane * 8;
    const float* cen = g_center + lane * 8;

    float4 a = *(const float4*)(v);
    float4 b = *(const float4*)(v + 4);
    float4 ca = *(const float4*)(cen);
    float4 cb = *(const float4*)(cen + 4);

    float ss = a.x*a.x + a.y*a.y + a.z*a.z + a.w*a.w
             + b.x*b.x + b.y*b.y + b.z*b.z + b.w*b.w;
    float dd = a.x*ca.x + a.y*ca.y + a.z*ca.z + a.w*ca.w
             + b.x*cb.x + b.y*cb.y + b.z*cb.z + b.w*cb.w;
    #pragma unroll
    for (int o = 16; o; o >>= 1) {
        ss += __shfl_down_sync(0xffffffffu, ss, o);
        dd += __shfl_down_sync(0xffffffffu, dd, o);
    }
    if (lane == 0) {
        float score = dd / fmaxf(sqrtf(ss), 1e-12f);
        atomicAdd((row <= N_SAMP) ? &sPos : &sNeg, score);
    }
    __syncthreads();
    if (threadIdx.x == 0) {
        if (sPos != 0.0f) atomicAdd(&g_scores[0], sPos);
        if (sNeg != 0.0f) atomicAdd(&g_scores[1], sNeg);
    }

    // restore invariant: mask zero for next call (512 blocks x 256 >= 40000)
    int g = blockIdx.x * 256 + threadIdx.x;
    if (g < N_NODES) g_mask[g] = 0;
}

// ---------------- kernel E: final loss ------------------------------------
__global__ void finalize_kernel(float* __restrict__ out) {
    float pos_mean = g_scores[0] * (1.0f / N_SAMP);
    float neg_mean = g_scores[1] * (1.0f / N_SAMP);
    float th = g_scores[2];
    float sp = 1.0f / (1.0f + expf(-(pos_mean - th)));   // T = 1
    float sn = 1.0f / (1.0f + expf(-(th - neg_mean)));
    float pl = logf(fmaxf(sp, 1e-12f));
    float nl = logf(fmaxf(sn, 1e-12f));
    out[0] = -pl - nl;
}

// ---------------- launch ---------------------------------------------------
extern "C" void kernel_launch(void* const* d_in, const int* in_sizes, int n_in,
                              void* d_out, int out_size) {
    const float* x    = (const float*)d_in[0];
    const int*   ei   = (const int*)d_in[1];     // int32 (JAX x64 disabled)
    const float* ea   = (const float*)d_in[2];
    const int*   pos  = (const int*)d_in[3];
    const int*   neg  = (const int*)d_in[4];
    const float* We   = (const float*)d_in[5];
    const float* be   = (const float*)d_in[6];
    const float* W1   = (const float*)d_in[7];
    const float* b1   = (const float*)d_in[8];
    const float* W2   = (const float*)d_in[9];
    const float* b2   = (const float*)d_in[10];
    const float* thr  = (const float*)d_in[11];
    float* out = (float*)d_out;

    const int* src = ei;            // edge_index[0]
    const int* dst = ei + N_EDGES;  // edge_index[1]

    build_mask_kernel<<<N_QUERY, IN_CH>>>(pos, neg);
    edge_filter_kernel<<<N_EDGES / 4 / 256, 256>>>(dst);
    edge_scatter_kernel<<<296, 256>>>(src, dst, ea, x, We, be);
    mlp_kernel<<<(N_QUERY + MROWS - 1) / MROWS, 256>>>(x, W1, b1, W2, b2);
    center_kernel<<<1, 256>>>(thr);
    score_kernel<<<N_SAMP / 4, 256>>>();
    finalize_kernel<<<1, 1>>>(out);
}